// round 3
// baseline (speedup 1.0000x reference)
#include <cuda_runtime.h>
#include <cstdint>
#include <cstddef>

#define BB 128
#define NN 2048
#define HH 64
#define SS 64

// ---------------- scratch (static device memory; no allocation) ----------------
__device__ __align__(256) float d_h0[(size_t)BB * HH * NN];   // 64 MB, [b][c][rank]
__device__ __align__(256) float d_h1[(size_t)BB * HH * NN];   // 64 MB
__device__ __align__(256) float d_agg0[BB * SS * HH];
__device__ __align__(256) float d_agg1[BB * SS * HH];
__device__ __align__(256) float d_agg2[BB * SS * HH];
__device__ __align__(256) float d_aggW[BB * SS * HH];         // bias + agg@W_bot, per layer
__device__ int            d_perm[BB * NN];
__device__ int            d_cs[BB * NN];                      // sorted cluster ids

// ---------------- prep: dtype-detect + per-batch counting sort by cluster ----------------
__global__ void prep_kernel(const void* __restrict__ cl) {
    __shared__ int cnt[SS];
    __shared__ int cur[SS];
    __shared__ int isll;
    int b = blockIdx.x, tid = threadIdx.x;
    if (tid == 0) {
        const long long* p = (const long long*)cl;
        int ok = 1;
        for (int i = 0; i < 16; i++) { long long v = p[i]; if (v < 0 || v >= SS) ok = 0; }
        isll = ok;
    }
    if (tid < SS) cnt[tid] = 0;
    __syncthreads();
    const long long* p64 = (const long long*)cl;
    const int*       p32 = (const int*)cl;
    int l = isll;
    for (int n = tid; n < NN; n += blockDim.x) {
        int s = l ? (int)p64[(size_t)b * NN + n] : p32[(size_t)b * NN + n];
        atomicAdd(&cnt[s], 1);
    }
    __syncthreads();
    if (tid == 0) {
        int run = 0;
        for (int s = 0; s < SS; s++) { int c = cnt[s]; cur[s] = run; run += c; }
    }
    __syncthreads();
    for (int n = tid; n < NN; n += blockDim.x) {
        int s = l ? (int)p64[(size_t)b * NN + n] : p32[(size_t)b * NN + n];
        int r = atomicAdd(&cur[s], 1);
        d_perm[b * NN + r] = n;
        d_cs[b * NN + r]   = s;
    }
}

__global__ void zero_aggs_kernel() {
    int i = blockIdx.x * blockDim.x + threadIdx.x;
    if (i < BB * SS * HH) { d_agg0[i] = 0.f; d_agg1[i] = 0.f; d_agg2[i] = 0.f; }
}

// ---------------- shared epilogue: LN -> relu -> (store h) -> warp-segmented max -> atomics ----------------
template <bool WRITE>
__device__ __forceinline__ void epilogue(float acc[HH], const float* gsm, const float* besm,
                                         int s, float* houtp, float* agg, int aggbase) {
    float sum = 0.f;
#pragma unroll
    for (int i = 0; i < HH; i++) sum += acc[i];
    float mu = sum * (1.0f / 64.0f);
    float ss = 0.f;
#pragma unroll
    for (int i = 0; i < HH; i++) { float d = acc[i] - mu; ss = fmaf(d, d, ss); }
    float rs = rsqrtf(ss * (1.0f / 64.0f) + 1e-5f);
#pragma unroll
    for (int i = 0; i < HH; i++) {
        float r = fmaxf(fmaf((acc[i] - mu) * rs, gsm[i], besm[i]), 0.0f);
        if (WRITE) houtp[(size_t)i * NN] = r;
        acc[i] = r;
    }
    // warp-segmented suffix-max (cluster ids nondecreasing over lanes thanks to the sort)
    const unsigned m = 0xffffffffu;
    int lane = threadIdx.x & 31;
    int s1  = __shfl_down_sync(m, s, 1);
    int s2  = __shfl_down_sync(m, s, 2);
    int s4  = __shfl_down_sync(m, s, 4);
    int s8  = __shfl_down_sync(m, s, 8);
    int s16 = __shfl_down_sync(m, s, 16);
    int sp  = __shfl_up_sync(m, s, 1);
    bool c1 = (s1 == s), c2 = (s2 == s), c4 = (s4 == s), c8 = (s8 == s), c16 = (s16 == s);
    bool leader = (lane == 0) || (sp != s);
#pragma unroll
    for (int i = 0; i < HH; i++) {
        float v = acc[i], u;
        u = __shfl_down_sync(m, v, 1);  if (c1)  v = fmaxf(v, u);
        u = __shfl_down_sync(m, v, 2);  if (c2)  v = fmaxf(v, u);
        u = __shfl_down_sync(m, v, 4);  if (c4)  v = fmaxf(v, u);
        u = __shfl_down_sync(m, v, 8);  if (c8)  v = fmaxf(v, u);
        u = __shfl_down_sync(m, v, 16); if (c16) v = fmaxf(v, u);
        if (leader) {
            // all values are >= 0 (post-ReLU), init is 0 -> signed-int max == float max
            atomicMax((int*)(agg + aggbase + i), __float_as_int(v));
        }
    }
}

// ---------------- layer 0: gather x via perm, 8->64 matvec, LN/relu, write h0 + agg0 ----------------
__global__ __launch_bounds__(256) void layer0_kernel(const float* __restrict__ x,
                                                     const float* __restrict__ W0,
                                                     const float* __restrict__ b0,
                                                     const float* __restrict__ g0,
                                                     const float* __restrict__ be0) {
    __shared__ float Wsm[8 * HH];
    __shared__ float bsm[HH], gsm[HH], besm[HH];
    int tid = threadIdx.x, b = blockIdx.y;
    int rank = blockIdx.x * 256 + tid;
    for (int i = tid; i < 8 * HH; i += 256) Wsm[i] = W0[i];
    if (tid < HH) { bsm[tid] = b0[tid]; gsm[tid] = g0[tid]; besm[tid] = be0[tid]; }
    __syncthreads();
    int n = d_perm[b * NN + rank];
    int s = d_cs[b * NN + rank];
    const float4* xp = (const float4*)(x + ((size_t)b * NN + n) * 8);
    float4 xa = xp[0], xb = xp[1];
    float xv[8] = {xa.x, xa.y, xa.z, xa.w, xb.x, xb.y, xb.z, xb.w};
    float acc[HH];
#pragma unroll
    for (int i = 0; i < HH; i++) acc[i] = bsm[i];
#pragma unroll
    for (int k = 0; k < 8; k++) {
        float h = xv[k];
        const float* wr = Wsm + k * HH;
#pragma unroll
        for (int i = 0; i < HH; i++) acc[i] = fmaf(h, wr[i], acc[i]);
    }
    epilogue<true>(acc, gsm, besm, s, d_h0 + ((size_t)b * HH) * NN + rank,
                   d_agg0, ((b << 6) + s) << 6);
}

// ---------------- tiny GEMM: aggW[b] = bias + agg[b] @ W_bot ----------------
__global__ __launch_bounds__(256) void smallmm_kernel(const float* __restrict__ Wfull,
                                                      const float* __restrict__ bias, int stage) {
    __shared__ float A[SS * HH];
    __shared__ float bsm[HH];
    const float* Wbot = Wfull + 64 * HH;   // rows 64..127 of the 128x64 weight
    const float* agg = (stage == 0) ? d_agg0 : d_agg1;
    int b = blockIdx.x, tid = threadIdx.x;
    for (int i = tid; i < SS * HH; i += 256) A[i] = agg[b * SS * HH + i];
    if (tid < HH) bsm[tid] = bias[tid];
    __syncthreads();
    for (int t = tid; t < SS * HH; t += 256) {
        int srow = t >> 6, c = t & 63;
        float a = bsm[c];
#pragma unroll 8
        for (int k = 0; k < HH; k++) a = fmaf(A[(srow << 6) + k], Wbot[(k << 6) + c], a);
        d_aggW[b * SS * HH + t] = a;
    }
}

// ---------------- layers 1/2: 64->64 matvec (h@W_top + aggW[s]), LN/relu, agg ----------------
template <int STAGE>
__global__ __launch_bounds__(256) void layer12_kernel(const float* __restrict__ W,
                                                      const float* __restrict__ g,
                                                      const float* __restrict__ be) {
    __shared__ float Wsm[HH * HH];
    __shared__ float gsm[HH], besm[HH];
    int tid = threadIdx.x, b = blockIdx.y;
    int rank = blockIdx.x * 256 + tid;
    for (int i = tid; i < (HH * HH) / 4; i += 256) ((float4*)Wsm)[i] = ((const float4*)W)[i];
    if (tid < HH) { gsm[tid] = g[tid]; besm[tid] = be[tid]; }
    __syncthreads();
    int s = d_cs[b * NN + rank];
    const float* aw = d_aggW + (((size_t)b * SS + s) << 6);
    float acc[HH];
#pragma unroll
    for (int i = 0; i < HH; i++) acc[i] = aw[i];   // bias already folded in
    const float* hp = ((STAGE == 1) ? d_h0 : d_h1) + ((size_t)b * HH) * NN + rank;
#pragma unroll 4
    for (int k = 0; k < HH; k++) {
        float h = hp[(size_t)k * NN];
        const float* wr = Wsm + k * HH;
#pragma unroll
        for (int i = 0; i < HH; i++) acc[i] = fmaf(h, wr[i], acc[i]);
    }
    float* houtp = (STAGE == 1) ? (d_h1 + ((size_t)b * HH) * NN + rank) : (float*)0;
    epilogue<(STAGE == 1)>(acc, gsm, besm, s, houtp,
                           (STAGE == 1) ? d_agg1 : d_agg2, ((b << 6) + s) << 6);
}

// ---------------- final: out[b,s,c]=out[b,s,64+c]=agg2[b,s,c]/max(||col||, eps) ----------------
__global__ void final_kernel(float* __restrict__ out) {
    int b = blockIdx.x;
    int c = threadIdx.x;   // 64 threads, one per channel
    const float* a = d_agg2 + b * SS * HH;
    float ss = 0.f;
#pragma unroll 8
    for (int s = 0; s < SS; s++) { float v = a[s * HH + c]; ss = fmaf(v, v, ss); }
    float inv = 1.0f / fmaxf(sqrtf(ss), 1e-12f);
    for (int s = 0; s < SS; s++) {
        float o = a[s * HH + c] * inv;
        out[((size_t)(b * SS + s)) * 128 + c]      = o;
        out[((size_t)(b * SS + s)) * 128 + 64 + c] = o;
    }
}

// ---------------- launch ----------------
extern "C" void kernel_launch(void* const* d_in, const int* in_sizes, int n_in,
                              void* d_out, int out_size) {
    const float* x  = (const float*)d_in[0];
    const void*  cl = d_in[1];
    const float* W0 = (const float*)d_in[2];
    const float* b0 = (const float*)d_in[3];
    const float* g0 = (const float*)d_in[4];
    const float* e0 = (const float*)d_in[5];
    const float* W1 = (const float*)d_in[6];
    const float* b1 = (const float*)d_in[7];
    const float* g1 = (const float*)d_in[8];
    const float* e1 = (const float*)d_in[9];
    const float* W2 = (const float*)d_in[10];
    const float* b2 = (const float*)d_in[11];
    const float* g2 = (const float*)d_in[12];
    const float* e2 = (const float*)d_in[13];
    float* out = (float*)d_out;

    prep_kernel<<<BB, 256>>>(cl);
    zero_aggs_kernel<<<(BB * SS * HH + 255) / 256, 256>>>();
    layer0_kernel<<<dim3(NN / 256, BB), 256>>>(x, W0, b0, g0, e0);
    smallmm_kernel<<<BB, 256>>>(W1, b1, 0);
    layer12_kernel<1><<<dim3(NN / 256, BB), 256>>>(W1, g1, e1);
    smallmm_kernel<<<BB, 256>>>(W2, b2, 1);
    layer12_kernel<2><<<dim3(NN / 256, BB), 256>>>(W2, g2, e2);
    final_kernel<<<BB, 64>>>(out);
}